// round 4
// baseline (speedup 1.0000x reference)
#include <cuda_runtime.h>
#include <cuda_bf16.h>

// Problem shape (fixed by the dataset): x:(B=16, D=1024), alphas/betas:(1, H=4)
#define D_DIM 1024
#define H_DIM 4
#define EPSILON 1e-8f
#define THREADS 512
#define QW 2                  // queries per warp
#define QPB 8                 // queries per block (16 warps / 4 heads * QW)
#define NT 8                  // float4 tiles per lane (8 * 4 = 32 keys per lane)
#define LOG2E 1.4426950408889634f

// rcp.approx + one Newton step: rel err ~2^-44, 3 instructions total.
__device__ __forceinline__ float frcp_fast(float d) {
    float r;
    asm("rcp.approx.f32 %0, %1;" : "=f"(r) : "f"(d));
    float e = __fmaf_rn(-d, r, 1.0f);
    return __fmaf_rn(r, e, r);
}

__device__ __forceinline__ float ex2_fast(float a) {
    float r;
    asm("ex2.approx.f32 %0, %1;" : "=f"(r) : "f"(a));
    return r;
}

__global__ __launch_bounds__(THREADS)
void flatt_kernel(const float* __restrict__ x,
                  const float* __restrict__ aq, const float* __restrict__ bq,
                  const float* __restrict__ ak, const float* __restrict__ bk,
                  const float* __restrict__ av, const float* __restrict__ bv,
                  float* __restrict__ out)
{
    __shared__ float4 sk4[H_DIM][D_DIM / 4];
    __shared__ float4 sv4[H_DIM][D_DIM / 4];
    __shared__ float4 sx4[D_DIM / 4];
    __shared__ float  satt[QPB][H_DIM];

    const int blocks_per_batch = D_DIM / QPB;   // 128
    const int b  = blockIdx.x / blocks_per_batch;
    const int i0 = (blockIdx.x % blocks_per_batch) * QPB;
    const float* sx = (const float*)sx4;

    // ---- Stage x and per-head k,v: one float2 per thread across 512 threads ----
    {
        const float2 xv = ((const float2*)(x + b * D_DIM))[threadIdx.x];
        ((float2*)sx4)[threadIdx.x] = xv;
#pragma unroll
        for (int h = 0; h < H_DIM; h++) {
            const float a1 = ak[h], b1 = bk[h];
            ((float2*)sk4[h])[threadIdx.x] =
                make_float2(fmaf(a1, xv.x, b1), fmaf(a1, xv.y, b1));
            const float a2 = av[h], b2 = bv[h];
            ((float2*)sv4[h])[threadIdx.x] =
                make_float2(fmaf(a2, xv.x, b2), fmaf(a2, xv.y, b2));
        }
    }
    __syncthreads();

    const int warp  = threadIdx.x >> 5;
    const int lane  = threadIdx.x & 31;
    const int qpair = warp >> 2;        // 0..3
    const int h     = warp & 3;         // head
    const int qi0   = i0 + qpair * QW;  // first query of this warp

    const float aqh = aq[h], bqh = bq[h];
    const float q0 = fmaf(aqh, sx[qi0 + 0], bqh);
    const float q1 = fmaf(aqh, sx[qi0 + 1], bqh);

    // ---- Pass 1: per-tile min distances for both queries (k-tile loaded once) ----
    float dt0[NT], dt1[NT];
#pragma unroll
    for (int t = 0; t < NT; t++) {
        const float4 kk = sk4[h][t * 32 + lane];
        float a0 = fabsf(kk.x - q0) + EPSILON;
        float a1 = fabsf(kk.y - q0) + EPSILON;
        float a2 = fabsf(kk.z - q0) + EPSILON;
        float a3 = fabsf(kk.w - q0) + EPSILON;
        dt0[t] = fminf(fminf(a0, a1), fminf(a2, a3));
        float c0 = fabsf(kk.x - q1) + EPSILON;
        float c1 = fabsf(kk.y - q1) + EPSILON;
        float c2 = fabsf(kk.z - q1) + EPSILON;
        float c3 = fabsf(kk.w - q1) + EPSILON;
        dt1[t] = fminf(fminf(c0, c1), fminf(c2, c3));
    }
    float dmin0 = dt0[0], dmin1 = dt1[0];
#pragma unroll
    for (int t = 1; t < NT; t++) {
        dmin0 = fminf(dmin0, dt0[t]);
        dmin1 = fminf(dmin1, dt1[t]);
    }
#pragma unroll
    for (int o = 16; o; o >>= 1) {
        dmin0 = fminf(dmin0, __shfl_xor_sync(0xffffffffu, dmin0, o));
        dmin1 = fminf(dmin1, __shfl_xor_sync(0xffffffffu, dmin1, o));
    }

    // ---- Pass 2 (per query): recompute d on live tiles only ----
    // Softmax shift m cancels exactly in acc/psum; terms with s < m - 80
    // contribute < e^-80 (~1e-35) and are dropped. Live in d-space: d < 1/(m-80).
#pragma unroll
    for (int qq = 0; qq < QW; qq++) {
        const float  q    = qq ? q1 : q0;
        const float* dt   = qq ? dt1 : dt0;
        const float  m    = frcp_fast(qq ? dmin1 : dmin0);
        const float  thr  = (m > 81.0f) ? frcp_fast(m - 80.0f) : 3.4e38f;
        const float  c    = -m * LOG2E;

        float ps0 = 0.f, ps1 = 0.f, ac0 = 0.f, ac1 = 0.f;
#pragma unroll
        for (int t = 0; t < NT; t++) {
            if (__any_sync(0xffffffffu, dt[t] < thr)) {
                const float4 kk = sk4[h][t * 32 + lane];
                const float4 vv = sv4[h][t * 32 + lane];
                float d0 = fabsf(kk.x - q) + EPSILON;
                float d1 = fabsf(kk.y - q) + EPSILON;
                float d2 = fabsf(kk.z - q) + EPSILON;
                float d3 = fabsf(kk.w - q) + EPSILON;
                float p0 = ex2_fast(fmaf(frcp_fast(d0), LOG2E, c));
                float p1 = ex2_fast(fmaf(frcp_fast(d1), LOG2E, c));
                float p2 = ex2_fast(fmaf(frcp_fast(d2), LOG2E, c));
                float p3 = ex2_fast(fmaf(frcp_fast(d3), LOG2E, c));
                ps0 += p0 + p2;
                ps1 += p1 + p3;
                ac0 = fmaf(p0, vv.x, ac0);
                ac1 = fmaf(p1, vv.y, ac1);
                ac0 = fmaf(p2, vv.z, ac0);
                ac1 = fmaf(p3, vv.w, ac1);
            }
        }
        float psum = ps0 + ps1;
        float acc  = ac0 + ac1;
#pragma unroll
        for (int o = 16; o; o >>= 1) {
            psum += __shfl_xor_sync(0xffffffffu, psum, o);
            acc  += __shfl_xor_sync(0xffffffffu, acc,  o);
        }
        if (lane == 0)
            satt[qpair * QW + qq][h] = (acc / psum) * 0.5f;  // 1/sqrt(H)=0.5
    }
    __syncthreads();

    // Combine heads + residual, one thread per query
    if (threadIdx.x < QPB) {
        int qq = i0 + threadIdx.x;
        float r = sx[qq];
#pragma unroll
        for (int h2 = 0; h2 < H_DIM; h2++) r += satt[threadIdx.x][h2];
        out[b * D_DIM + qq] = r;
    }
}

extern "C" void kernel_launch(void* const* d_in, const int* in_sizes, int n_in,
                              void* d_out, int out_size)
{
    const float* x  = (const float*)d_in[0];
    const float* aq = (const float*)d_in[1];
    const float* bq = (const float*)d_in[2];
    const float* ak = (const float*)d_in[3];
    const float* bk = (const float*)d_in[4];
    const float* av = (const float*)d_in[5];
    const float* bv = (const float*)d_in[6];
    float* out = (float*)d_out;

    const int B = in_sizes[0] / D_DIM;        // 16
    const int grid = B * (D_DIM / QPB);       // 2048 blocks

    flatt_kernel<<<grid, THREADS>>>(x, aq, bq, ak, bk, av, bv, out);
}

// round 5
// speedup vs baseline: 1.1447x; 1.1447x over previous
#include <cuda_runtime.h>
#include <cuda_bf16.h>

// Problem shape (fixed by the dataset): x:(B=16, D=1024), alphas/betas:(1, H=4)
#define D_DIM 1024
#define H_DIM 4
#define EPSILON 1e-8f
#define THREADS 256
#define QPB 2                 // queries per block (8 warps = QPB * H_DIM work items)
#define NT 8                  // float4 tiles per lane (8 * 4 = 32 keys per lane)
#define LOG2E 1.4426950408889634f

// rcp.approx + one Newton step: rel err ~2^-44, 3 instructions total.
__device__ __forceinline__ float frcp_fast(float d) {
    float r;
    asm("rcp.approx.f32 %0, %1;" : "=f"(r) : "f"(d));
    float e = __fmaf_rn(-d, r, 1.0f);
    return __fmaf_rn(r, e, r);
}

__device__ __forceinline__ float ex2_fast(float a) {
    float r;
    asm("ex2.approx.f32 %0, %1;" : "=f"(r) : "f"(a));
    return r;
}

__global__ __launch_bounds__(THREADS)
void flatt_kernel(const float* __restrict__ x,
                  const float* __restrict__ aq, const float* __restrict__ bq,
                  const float* __restrict__ ak, const float* __restrict__ bk,
                  const float* __restrict__ av, const float* __restrict__ bv,
                  float* __restrict__ out)
{
    __shared__ float4 sk4[H_DIM][D_DIM / 4];
    __shared__ float4 sv4[H_DIM][D_DIM / 4];
    __shared__ float  satt[QPB][H_DIM];

    const int blocks_per_batch = D_DIM / QPB;
    const int b  = blockIdx.x / blocks_per_batch;
    const int i0 = (blockIdx.x % blocks_per_batch) * QPB;
    const float* xb = x + b * D_DIM;

    // ---- Stage per-head k,v (vectorized: 1 float4 of x per thread) ----
    {
        const float4 xv = __ldg((const float4*)xb + threadIdx.x);
#pragma unroll
        for (int h = 0; h < H_DIM; h++) {
            const float a1 = ak[h], b1 = bk[h];
            sk4[h][threadIdx.x] = make_float4(fmaf(a1, xv.x, b1), fmaf(a1, xv.y, b1),
                                              fmaf(a1, xv.z, b1), fmaf(a1, xv.w, b1));
            const float a2 = av[h], b2 = bv[h];
            sv4[h][threadIdx.x] = make_float4(fmaf(a2, xv.x, b2), fmaf(a2, xv.y, b2),
                                              fmaf(a2, xv.z, b2), fmaf(a2, xv.w, b2));
        }
    }
    __syncthreads();

    const int warp = threadIdx.x >> 5;
    const int lane = threadIdx.x & 31;
    const int qloc = warp >> 2;        // 0..QPB-1
    const int qi   = i0 + qloc;        // query index within row
    const int h    = warp & 3;         // head

    const float q = fmaf(aq[h], __ldg(xb + qi), bq[h]);

    // ---- Pass 1: per-tile min of |k - q| (eps hoisted out; fabs folds into FMNMX) ----
    float dt[NT];
#pragma unroll
    for (int t = 0; t < NT; t++) {
        const float4 kk = sk4[h][t * 32 + lane];
        float a0 = kk.x - q, a1 = kk.y - q, a2 = kk.z - q, a3 = kk.w - q;
        dt[t] = fminf(fminf(fabsf(a0), fabsf(a1)), fminf(fabsf(a2), fabsf(a3)));
    }
    float dmin = dt[0];
#pragma unroll
    for (int t = 1; t < NT; t++) dmin = fminf(dmin, dt[t]);
#pragma unroll
    for (int o = 16; o; o >>= 1)
        dmin = fminf(dmin, __shfl_xor_sync(0xffffffffu, dmin, o));
    dmin += EPSILON;                   // min(|.|)+eps == min(|.|+eps)

    // Softmax shift m cancels exactly in acc/psum; terms with s < m - 80
    // contribute < e^-80 and are dropped. Live in d-space: |k-q| < 1/(m-80)
    // (conservative: compares raw min, eps only shrinks true d-space further... 
    //  actually raw < thr admits a superset of live elements — safe).
    const float m   = frcp_fast(dmin);
    const float thr = (m > 81.0f) ? frcp_fast(m - 80.0f) : 3.4e38f;
    const float c   = -m * LOG2E;

    // ---- Pass 2: recompute d on live tiles only; rcp+Newton+exp there ----
    float ps0 = 0.f, ps1 = 0.f, ac0 = 0.f, ac1 = 0.f;
#pragma unroll
    for (int t = 0; t < NT; t++) {
        if (__any_sync(0xffffffffu, dt[t] < thr)) {
            const float4 kk = sk4[h][t * 32 + lane];
            const float4 vv = sv4[h][t * 32 + lane];
            float d0 = fabsf(kk.x - q) + EPSILON;
            float d1 = fabsf(kk.y - q) + EPSILON;
            float d2 = fabsf(kk.z - q) + EPSILON;
            float d3 = fabsf(kk.w - q) + EPSILON;
            float p0 = ex2_fast(fmaf(frcp_fast(d0), LOG2E, c));
            float p1 = ex2_fast(fmaf(frcp_fast(d1), LOG2E, c));
            float p2 = ex2_fast(fmaf(frcp_fast(d2), LOG2E, c));
            float p3 = ex2_fast(fmaf(frcp_fast(d3), LOG2E, c));
            ps0 += p0 + p2;
            ps1 += p1 + p3;
            ac0 = fmaf(p0, vv.x, ac0);
            ac1 = fmaf(p1, vv.y, ac1);
            ac0 = fmaf(p2, vv.z, ac0);
            ac1 = fmaf(p3, vv.w, ac1);
        }
    }
    float psum = ps0 + ps1;
    float acc  = ac0 + ac1;
#pragma unroll
    for (int o = 16; o; o >>= 1) {
        psum += __shfl_xor_sync(0xffffffffu, psum, o);
        acc  += __shfl_xor_sync(0xffffffffu, acc,  o);
    }

    if (lane == 0)
        satt[qloc][h] = (acc / psum) * 0.5f;   // 1/sqrt(H)=0.5 folded here
    __syncthreads();

    // Combine heads + residual, one thread per query
    if (threadIdx.x < QPB) {
        int qq = i0 + threadIdx.x;
        float r = __ldg(xb + qq);
#pragma unroll
        for (int h2 = 0; h2 < H_DIM; h2++) r += satt[threadIdx.x][h2];
        out[b * D_DIM + qq] = r;
    }
}

extern "C" void kernel_launch(void* const* d_in, const int* in_sizes, int n_in,
                              void* d_out, int out_size)
{
    const float* x  = (const float*)d_in[0];
    const float* aq = (const float*)d_in[1];
    const float* bq = (const float*)d_in[2];
    const float* ak = (const float*)d_in[3];
    const float* bk = (const float*)d_in[4];
    const float* av = (const float*)d_in[5];
    const float* bv = (const float*)d_in[6];
    float* out = (float*)d_out;

    const int B = in_sizes[0] / D_DIM;     // 16
    const int grid = B * (D_DIM / QPB);    // 8192 blocks

    flatt_kernel<<<grid, THREADS>>>(x, aq, bq, ak, bk, av, bv, out);
}

// round 6
// speedup vs baseline: 1.2897x; 1.1266x over previous
#include <cuda_runtime.h>
#include <cuda_bf16.h>

// Problem shape (fixed by the dataset): x:(B=16, D=1024), alphas/betas:(1, H=4)
#define D_DIM 1024
#define H_DIM 4
#define EPSILON 1e-8f
#define THREADS 256
#define QPB 4                 // queries per block (8 warps = QPB * 2 head-pairs)
#define NT 8                  // float4 tiles per lane (8 * 4 = 32 keys per lane)
#define LOG2E 1.4426950408889634f

typedef unsigned long long u64;

// rcp.approx + one Newton step: rel err ~2^-44, 3 instructions total.
__device__ __forceinline__ float frcp_fast(float d) {
    float r;
    asm("rcp.approx.f32 %0, %1;" : "=f"(r) : "f"(d));
    float e = __fmaf_rn(-d, r, 1.0f);
    return __fmaf_rn(r, e, r);
}
__device__ __forceinline__ float ex2_fast(float a) {
    float r;
    asm("ex2.approx.f32 %0, %1;" : "=f"(r) : "f"(a));
    return r;
}
// Packed f32x2 helpers (sm_100a): pack/unpack are register-pair aliases (free).
__device__ __forceinline__ u64 pack2(float lo, float hi) {
    u64 r;
    asm("mov.b64 %0, {%1, %2};" : "=l"(r) : "f"(lo), "f"(hi));
    return r;
}
__device__ __forceinline__ float2 unpack2(u64 v) {
    float2 r;
    asm("mov.b64 {%0, %1}, %2;" : "=f"(r.x), "=f"(r.y) : "l"(v));
    return r;
}
__device__ __forceinline__ u64 fma2(u64 a, u64 b, u64 c) {
    u64 r;
    asm("fma.rn.f32x2 %0, %1, %2, %3;" : "=l"(r) : "l"(a), "l"(b), "l"(c));
    return r;
}
__device__ __forceinline__ u64 add2(u64 a, u64 b) {
    u64 r;
    asm("add.rn.f32x2 %0, %1, %2;" : "=l"(r) : "l"(a), "l"(b));
    return r;
}

__global__ __launch_bounds__(THREADS)
void flatt_kernel(const float* __restrict__ x,
                  const float* __restrict__ aq, const float* __restrict__ bq,
                  const float* __restrict__ ak, const float* __restrict__ bk,
                  const float* __restrict__ av, const float* __restrict__ bv,
                  float* __restrict__ out)
{
    __shared__ float4 sx4[D_DIM / 4];
    __shared__ float  satt[QPB][2];

    const int blocks_per_batch = D_DIM / QPB;     // 256
    const int b  = blockIdx.x / blocks_per_batch;
    const int i0 = (blockIdx.x % blocks_per_batch) * QPB;
    const float* xb = x + b * D_DIM;
    const float* sx = (const float*)sx4;

    // Stage only x (4KB). k, v are rank-1 in x and never materialized.
    sx4[threadIdx.x] = __ldg((const float4*)xb + threadIdx.x);
    __syncthreads();

    const int warp = threadIdx.x >> 5;
    const int lane = threadIdx.x & 31;
    const int qloc = warp >> 1;         // 0..QPB-1
    const int hp   = warp & 1;          // head pair
    const int h0   = hp * 2, h1 = h0 + 1;
    const int qi   = i0 + qloc;

    const float xq  = sx[qi];
    const float q0  = fmaf(aq[h0], xq, bq[h0]);
    const float q1  = fmaf(aq[h1], xq, bq[h1]);
    const float a0  = ak[h0], a1  = ak[h1];
    const float bk0 = bk[h0], bk1 = bk[h1];

    const u64 aP0 = pack2(a0, a0),  bP0 = pack2(bk0, bk0), nqP0 = pack2(-q0, -q0);
    const u64 aP1 = pack2(a1, a1),  bP1 = pack2(bk1, bk1), nqP1 = pack2(-q1, -q1);

    // ---- Pass 1: per-tile min |k - q| for both heads; x-tile loaded ONCE ----
    // k = fma(ak, x, bk) then + (-q): bit-identical to the reference arithmetic.
    float dt0[NT], dt1[NT];
#pragma unroll
    for (int t = 0; t < NT; t++) {
        const float4 xx = sx4[t * 32 + lane];
        const u64 x01 = pack2(xx.x, xx.y);
        const u64 x23 = pack2(xx.z, xx.w);
        {
            const float2 r01 = unpack2(add2(fma2(aP0, x01, bP0), nqP0));
            const float2 r23 = unpack2(add2(fma2(aP0, x23, bP0), nqP0));
            dt0[t] = fminf(fminf(fabsf(r01.x), fabsf(r01.y)),
                           fminf(fabsf(r23.x), fabsf(r23.y)));
        }
        {
            const float2 r01 = unpack2(add2(fma2(aP1, x01, bP1), nqP1));
            const float2 r23 = unpack2(add2(fma2(aP1, x23, bP1), nqP1));
            dt1[t] = fminf(fminf(fabsf(r01.x), fabsf(r01.y)),
                           fminf(fabsf(r23.x), fabsf(r23.y)));
        }
    }
    float dmin0 = dt0[0], dmin1 = dt1[0];
#pragma unroll
    for (int t = 1; t < NT; t++) {
        dmin0 = fminf(dmin0, dt0[t]);
        dmin1 = fminf(dmin1, dt1[t]);
    }
#pragma unroll
    for (int o = 16; o; o >>= 1) {
        dmin0 = fminf(dmin0, __shfl_xor_sync(0xffffffffu, dmin0, o));
        dmin1 = fminf(dmin1, __shfl_xor_sync(0xffffffffu, dmin1, o));
    }

    // Max scores (shift points). Terms with s < m - 80 contribute < e^-80: dropped.
    // Liveness on raw |k-q|: raw < 1/(m-80) is a superset of the true live set.
    const float m0 = frcp_fast(dmin0 + EPSILON);
    const float m1 = frcp_fast(dmin1 + EPSILON);
    const float rthr0 = (m0 > 81.0f) ? frcp_fast(m0 - 80.0f) : 3.4e38f;
    const float rthr1 = (m1 > 81.0f) ? frcp_fast(m1 - 80.0f) : 3.4e38f;
    const float c0 = -m0 * LOG2E;
    const float c1 = -m1 * LOG2E;

    // ---- Pass 2: live tiles only. v eliminated: S0 = sum p, S1 = sum p*x ----
    float S00 = 0.f, S10 = 0.f;     // head h0
    float S01 = 0.f, S11 = 0.f;     // head h1
#pragma unroll
    for (int t = 0; t < NT; t++) {
        const bool live = (dt0[t] < rthr0) || (dt1[t] < rthr1);
        if (__any_sync(0xffffffffu, live)) {
            const float4 xx = sx4[t * 32 + lane];
            {   // head h0
                float k0 = fmaf(a0, xx.x, bk0), k1 = fmaf(a0, xx.y, bk0);
                float k2 = fmaf(a0, xx.z, bk0), k3 = fmaf(a0, xx.w, bk0);
                float d0 = fabsf(k0 - q0) + EPSILON;
                float d1 = fabsf(k1 - q0) + EPSILON;
                float d2 = fabsf(k2 - q0) + EPSILON;
                float d3 = fabsf(k3 - q0) + EPSILON;
                float p0 = ex2_fast(fmaf(frcp_fast(d0), LOG2E, c0));
                float p1 = ex2_fast(fmaf(frcp_fast(d1), LOG2E, c0));
                float p2 = ex2_fast(fmaf(frcp_fast(d2), LOG2E, c0));
                float p3 = ex2_fast(fmaf(frcp_fast(d3), LOG2E, c0));
                S00 += (p0 + p1) + (p2 + p3);
                S10 = fmaf(p0, xx.x, S10);
                S10 = fmaf(p1, xx.y, S10);
                S10 = fmaf(p2, xx.z, S10);
                S10 = fmaf(p3, xx.w, S10);
            }
            {   // head h1
                float k0 = fmaf(a1, xx.x, bk1), k1 = fmaf(a1, xx.y, bk1);
                float k2 = fmaf(a1, xx.z, bk1), k3 = fmaf(a1, xx.w, bk1);
                float d0 = fabsf(k0 - q1) + EPSILON;
                float d1 = fabsf(k1 - q1) + EPSILON;
                float d2 = fabsf(k2 - q1) + EPSILON;
                float d3 = fabsf(k3 - q1) + EPSILON;
                float p0 = ex2_fast(fmaf(frcp_fast(d0), LOG2E, c1));
                float p1 = ex2_fast(fmaf(frcp_fast(d1), LOG2E, c1));
                float p2 = ex2_fast(fmaf(frcp_fast(d2), LOG2E, c1));
                float p3 = ex2_fast(fmaf(frcp_fast(d3), LOG2E, c1));
                S01 += (p0 + p1) + (p2 + p3);
                S11 = fmaf(p0, xx.x, S11);
                S11 = fmaf(p1, xx.y, S11);
                S11 = fmaf(p2, xx.z, S11);
                S11 = fmaf(p3, xx.w, S11);
            }
        }
    }
#pragma unroll
    for (int o = 16; o; o >>= 1) {
        S00 += __shfl_xor_sync(0xffffffffu, S00, o);
        S10 += __shfl_xor_sync(0xffffffffu, S10, o);
        S01 += __shfl_xor_sync(0xffffffffu, S01, o);
        S11 += __shfl_xor_sync(0xffffffffu, S11, o);
    }

    if (lane == 0) {
        // att_h = (av*S1 + bv*S0)/S0 = av*(S1/S0) + bv ; 1/sqrt(H)=0.5 folded
        float att0 = fmaf(av[h0], S10 / S00, bv[h0]);
        float att1 = fmaf(av[h1], S11 / S01, bv[h1]);
        satt[qloc][hp] = 0.5f * (att0 + att1);
    }
    __syncthreads();

    if (threadIdx.x < QPB) {
        int qq = i0 + threadIdx.x;
        out[b * D_DIM + qq] = sx[qq] + satt[threadIdx.x][0] + satt[threadIdx.x][1];
    }
}

extern "C" void kernel_launch(void* const* d_in, const int* in_sizes, int n_in,
                              void* d_out, int out_size)
{
    const float* x  = (const float*)d_in[0];
    const float* aq = (const float*)d_in[1];
    const float* bq = (const float*)d_in[2];
    const float* ak = (const float*)d_in[3];
    const float* bk = (const float*)d_in[4];
    const float* av = (const float*)d_in[5];
    const float* bv = (const float*)d_in[6];
    float* out = (float*)d_out;

    const int B = in_sizes[0] / D_DIM;     // 16
    const int grid = B * (D_DIM / QPB);    // 4096 blocks

    flatt_kernel<<<grid, THREADS>>>(x, aq, bq, ak, bk, av, bv, out);
}